// round 1
// baseline (speedup 1.0000x reference)
#include <cuda_runtime.h>
#include <math.h>

#define D_MODEL 1024
#define N_HEADS 16
#define HEAD_DIM 64
#define D_FF 4096
#define BB 2
#define TT 2048
#define ROWS (BB * TT)   // 4096
#define LN_EPS 1e-5f

// ---------------- scratch (static device globals; no allocation) ----------------
__device__ float g_h  [ROWS * D_MODEL];
__device__ float g_q  [ROWS * D_MODEL];
__device__ float g_k  [ROWS * D_MODEL];
__device__ float g_v  [ROWS * D_MODEL];
__device__ float g_ctx[ROWS * D_MODEL];
__device__ float g_x1 [ROWS * D_MODEL];
__device__ float g_h2 [ROWS * D_MODEL];
__device__ float g_ff [ROWS * D_FF];

// ---------------- LayerNorm: one block per row, 256 threads ----------------
__global__ __launch_bounds__(256) void ln_kernel(
    const float* __restrict__ x, const float* __restrict__ g,
    const float* __restrict__ b, float* __restrict__ y)
{
    const int row = blockIdx.x;
    const int tid = threadIdx.x;
    const float4* xr = (const float4*)(x + (size_t)row * D_MODEL);
    float4 v = xr[tid];
    float s  = v.x + v.y + v.z + v.w;
    float ss = v.x*v.x + v.y*v.y + v.z*v.z + v.w*v.w;
    #pragma unroll
    for (int o = 16; o > 0; o >>= 1) {
        s  += __shfl_xor_sync(0xffffffffu, s, o);
        ss += __shfl_xor_sync(0xffffffffu, ss, o);
    }
    __shared__ float wsum[8], wsq[8];
    const int w = tid >> 5, l = tid & 31;
    if (l == 0) { wsum[w] = s; wsq[w] = ss; }
    __syncthreads();
    s = 0.f; ss = 0.f;
    #pragma unroll
    for (int i = 0; i < 8; i++) { s += wsum[i]; ss += wsq[i]; }
    const float mean = s * (1.f / D_MODEL);
    const float var  = ss * (1.f / D_MODEL) - mean * mean;
    const float rstd = rsqrtf(var + LN_EPS);
    const float4 g4 = ((const float4*)g)[tid];
    const float4 b4 = ((const float4*)b)[tid];
    float4 o;
    o.x = (v.x - mean) * rstd * g4.x + b4.x;
    o.y = (v.y - mean) * rstd * g4.y + b4.y;
    o.z = (v.z - mean) * rstd * g4.z + b4.z;
    o.w = (v.w - mean) * rstd * g4.w + b4.w;
    ((float4*)(y + (size_t)row * D_MODEL))[tid] = o;
}

// ---------------- GEMM: C[M,N] = A[M,K] @ W[N,K]^T + bias, fused epilogue ----------------
// EPI: 0 = none, 1 = exact GELU, 2 = + residual
template<int EPI>
__global__ __launch_bounds__(256) void gemm_kernel(
    const float* __restrict__ A, const float* __restrict__ W,
    const float* __restrict__ bias, const float* __restrict__ res,
    float* __restrict__ C, int M, int N, int K)
{
    __shared__ float As[16][128];
    __shared__ float Ws[16][128];
    const int tid = threadIdx.x;
    const int bm = blockIdx.y * 128, bn = blockIdx.x * 128;
    const int lr = tid >> 1;          // 0..127 (tile row)
    const int lc = (tid & 1) * 8;     // 0 or 8 (k offset)
    const float* Aptr = A + (size_t)(bm + lr) * K + lc;
    const float* Wptr = W + (size_t)(bn + lr) * K + lc;
    const int tx = tid & 15, ty = tid >> 4;
    const int r0 = ty * 8, c0 = tx * 8;
    float acc[8][8] = {};

    for (int k0 = 0; k0 < K; k0 += 16) {
        float4 a0 = *(const float4*)(Aptr + k0);
        float4 a1 = *(const float4*)(Aptr + k0 + 4);
        float4 w0 = *(const float4*)(Wptr + k0);
        float4 w1 = *(const float4*)(Wptr + k0 + 4);
        As[lc+0][lr] = a0.x; As[lc+1][lr] = a0.y; As[lc+2][lr] = a0.z; As[lc+3][lr] = a0.w;
        As[lc+4][lr] = a1.x; As[lc+5][lr] = a1.y; As[lc+6][lr] = a1.z; As[lc+7][lr] = a1.w;
        Ws[lc+0][lr] = w0.x; Ws[lc+1][lr] = w0.y; Ws[lc+2][lr] = w0.z; Ws[lc+3][lr] = w0.w;
        Ws[lc+4][lr] = w1.x; Ws[lc+5][lr] = w1.y; Ws[lc+6][lr] = w1.z; Ws[lc+7][lr] = w1.w;
        __syncthreads();
        #pragma unroll
        for (int kk = 0; kk < 16; kk++) {
            float4 af0 = *(const float4*)&As[kk][r0];
            float4 af1 = *(const float4*)&As[kk][r0 + 4];
            float4 bf0 = *(const float4*)&Ws[kk][c0];
            float4 bf1 = *(const float4*)&Ws[kk][c0 + 4];
            float a[8] = {af0.x, af0.y, af0.z, af0.w, af1.x, af1.y, af1.z, af1.w};
            float w[8] = {bf0.x, bf0.y, bf0.z, bf0.w, bf1.x, bf1.y, bf1.z, bf1.w};
            #pragma unroll
            for (int i = 0; i < 8; i++)
                #pragma unroll
                for (int j = 0; j < 8; j++)
                    acc[i][j] += a[i] * w[j];
        }
        __syncthreads();
    }

    #pragma unroll
    for (int i = 0; i < 8; i++) {
        const int gr = bm + r0 + i;
        #pragma unroll
        for (int j = 0; j < 8; j++) {
            const int gc = bn + c0 + j;
            float val = acc[i][j] + bias[gc];
            if (EPI == 1) {
                val = 0.5f * val * (1.f + erff(val * 0.70710678118654752440f));
            } else if (EPI == 2) {
                val += res[(size_t)gr * N + gc];
            }
            C[(size_t)gr * N + gc] = val;
        }
    }
}

// ---------------- Flash attention (causal): CTA = (qtile64, head, batch) ----------------
#define APAD 65
#define ATTN_SMEM (4 * 64 * APAD * (int)sizeof(float))

__global__ __launch_bounds__(256) void attn_kernel(
    const float* __restrict__ Q, const float* __restrict__ K,
    const float* __restrict__ V, float* __restrict__ O)
{
    extern __shared__ float sm[];
    float* Qs = sm;
    float* Ks = sm + 64 * APAD;
    float* Vs = sm + 2 * 64 * APAD;
    float* Ps = sm + 3 * 64 * APAD;

    const int qt = blockIdx.x, h = blockIdx.y, b = blockIdx.z;
    const int tid = threadIdx.x;
    const int tx = tid & 15, ty = tid >> 4;   // rows ty*4.., cols/dims tx*4..
    const int q0 = qt * 64;
    const size_t base = (size_t)b * TT * D_MODEL + (size_t)h * HEAD_DIM;

    // load Q tile (64 rows x 64 dims)
    #pragma unroll
    for (int i = 0; i < 4; i++) {
        int lin = tid + i * 256;     // float4 units: 64 rows * 16
        int row = lin >> 4, c4 = lin & 15;
        float4 qv = *(const float4*)(Q + base + (size_t)(q0 + row) * D_MODEL + c4 * 4);
        float* d = &Qs[row * APAD + c4 * 4];
        d[0] = qv.x; d[1] = qv.y; d[2] = qv.z; d[3] = qv.w;
    }

    float m_run[4] = {-1e30f, -1e30f, -1e30f, -1e30f};
    float l_run[4] = {};
    float o[4][4] = {};

    for (int kt = 0; kt <= qt; kt++) {
        const int k0 = kt * 64;
        __syncthreads();   // prev iter consumers done; also fences Qs on first iter
        #pragma unroll
        for (int i = 0; i < 4; i++) {
            int lin = tid + i * 256;
            int row = lin >> 4, c4 = lin & 15;
            const size_t goff = base + (size_t)(k0 + row) * D_MODEL + c4 * 4;
            float4 kv = *(const float4*)(K + goff);
            float4 vv = *(const float4*)(V + goff);
            float* dk = &Ks[row * APAD + c4 * 4];
            float* dv = &Vs[row * APAD + c4 * 4];
            dk[0] = kv.x; dk[1] = kv.y; dk[2] = kv.z; dk[3] = kv.w;
            dv[0] = vv.x; dv[1] = vv.y; dv[2] = vv.z; dv[3] = vv.w;
        }
        __syncthreads();

        // S = Q K^T (4x4 micro-tile)
        float s[4][4] = {};
        #pragma unroll 4
        for (int d = 0; d < 64; d++) {
            float a[4], kb[4];
            #pragma unroll
            for (int i = 0; i < 4; i++) a[i]  = Qs[(ty * 4 + i) * APAD + d];
            #pragma unroll
            for (int j = 0; j < 4; j++) kb[j] = Ks[(tx * 4 + j) * APAD + d];
            #pragma unroll
            for (int i = 0; i < 4; i++)
                #pragma unroll
                for (int j = 0; j < 4; j++)
                    s[i][j] += a[i] * kb[j];
        }

        // scale + causal mask (matches ref: masked entries exactly -1e9)
        if (kt == qt) {
            #pragma unroll
            for (int i = 0; i < 4; i++)
                #pragma unroll
                for (int j = 0; j < 4; j++) {
                    const int qr = ty * 4 + i, kc = tx * 4 + j;
                    s[i][j] = (kc > qr) ? -1e9f : s[i][j] * 0.125f;
                }
        } else {
            #pragma unroll
            for (int i = 0; i < 4; i++)
                #pragma unroll
                for (int j = 0; j < 4; j++) s[i][j] *= 0.125f;
        }

        // online softmax per row (reduce over 16 tx lanes)
        float oscale[4];
        #pragma unroll
        for (int i = 0; i < 4; i++) {
            float mt = fmaxf(fmaxf(s[i][0], s[i][1]), fmaxf(s[i][2], s[i][3]));
            mt = fmaxf(mt, __shfl_xor_sync(0xffffffffu, mt, 1));
            mt = fmaxf(mt, __shfl_xor_sync(0xffffffffu, mt, 2));
            mt = fmaxf(mt, __shfl_xor_sync(0xffffffffu, mt, 4));
            mt = fmaxf(mt, __shfl_xor_sync(0xffffffffu, mt, 8));
            const float mn = fmaxf(m_run[i], mt);
            const float esc = expf(m_run[i] - mn);
            float ps = 0.f;
            #pragma unroll
            for (int j = 0; j < 4; j++) {
                const float p = expf(s[i][j] - mn);
                Ps[(ty * 4 + i) * APAD + tx * 4 + j] = p;
                ps += p;
            }
            ps += __shfl_xor_sync(0xffffffffu, ps, 1);
            ps += __shfl_xor_sync(0xffffffffu, ps, 2);
            ps += __shfl_xor_sync(0xffffffffu, ps, 4);
            ps += __shfl_xor_sync(0xffffffffu, ps, 8);
            l_run[i] = l_run[i] * esc + ps;
            m_run[i] = mn;
            oscale[i] = esc;
        }
        #pragma unroll
        for (int i = 0; i < 4; i++)
            #pragma unroll
            for (int dd = 0; dd < 4; dd++) o[i][dd] *= oscale[i];

        __syncwarp();   // Ps row producers/consumers share a half-warp

        // O += P @ V
        #pragma unroll 4
        for (int j = 0; j < 64; j++) {
            float pv[4], vv[4];
            #pragma unroll
            for (int i = 0; i < 4; i++)  pv[i]  = Ps[(ty * 4 + i) * APAD + j];
            #pragma unroll
            for (int dd = 0; dd < 4; dd++) vv[dd] = Vs[j * APAD + tx * 4 + dd];
            #pragma unroll
            for (int i = 0; i < 4; i++)
                #pragma unroll
                for (int dd = 0; dd < 4; dd++)
                    o[i][dd] += pv[i] * vv[dd];
        }
    }

    // finalize + store
    #pragma unroll
    for (int i = 0; i < 4; i++) {
        const float inv = 1.f / l_run[i];
        float4 ov;
        ov.x = o[i][0] * inv; ov.y = o[i][1] * inv;
        ov.z = o[i][2] * inv; ov.w = o[i][3] * inv;
        *(float4*)(O + base + (size_t)(q0 + ty * 4 + i) * D_MODEL + tx * 4) = ov;
    }
}

// ---------------- launch ----------------
extern "C" void kernel_launch(void* const* d_in, const int* in_sizes, int n_in,
                              void* d_out, int out_size)
{
    const float* x     = (const float*)d_in[0];
    // d_in[1] = mask (bool) — causality implemented analytically, unused
    const float* wq_w  = (const float*)d_in[2];
    const float* wq_b  = (const float*)d_in[3];
    const float* wk_w  = (const float*)d_in[4];
    const float* wk_b  = (const float*)d_in[5];
    const float* wv_w  = (const float*)d_in[6];
    const float* wv_b  = (const float*)d_in[7];
    const float* wo_w  = (const float*)d_in[8];
    const float* wo_b  = (const float*)d_in[9];
    const float* fc1_w = (const float*)d_in[10];
    const float* fc1_b = (const float*)d_in[11];
    const float* fc2_w = (const float*)d_in[12];
    const float* fc2_b = (const float*)d_in[13];
    const float* ln1_g = (const float*)d_in[14];
    const float* ln1_b = (const float*)d_in[15];
    const float* ln2_g = (const float*)d_in[16];
    const float* ln2_b = (const float*)d_in[17];
    float* out = (float*)d_out;

    float *h, *q, *k, *v, *ctx, *x1, *h2, *ff;
    cudaGetSymbolAddress((void**)&h,   g_h);
    cudaGetSymbolAddress((void**)&q,   g_q);
    cudaGetSymbolAddress((void**)&k,   g_k);
    cudaGetSymbolAddress((void**)&v,   g_v);
    cudaGetSymbolAddress((void**)&ctx, g_ctx);
    cudaGetSymbolAddress((void**)&x1,  g_x1);
    cudaGetSymbolAddress((void**)&h2,  g_h2);
    cudaGetSymbolAddress((void**)&ff,  g_ff);

    cudaFuncSetAttribute(attn_kernel, cudaFuncAttributeMaxDynamicSharedMemorySize, ATTN_SMEM);

    // 1) ln1
    ln_kernel<<<ROWS, 256>>>(x, ln1_g, ln1_b, h);
    // 2) QKV projections
    const dim3 gD(D_MODEL / 128, ROWS / 128);
    gemm_kernel<0><<<gD, 256>>>(h, wq_w, wq_b, nullptr, q, ROWS, D_MODEL, D_MODEL);
    gemm_kernel<0><<<gD, 256>>>(h, wk_w, wk_b, nullptr, k, ROWS, D_MODEL, D_MODEL);
    gemm_kernel<0><<<gD, 256>>>(h, wv_w, wv_b, nullptr, v, ROWS, D_MODEL, D_MODEL);
    // 3) causal flash attention
    attn_kernel<<<dim3(TT / 64, N_HEADS, BB), 256, ATTN_SMEM>>>(q, k, v, ctx);
    // 4) output projection + residual
    gemm_kernel<2><<<gD, 256>>>(ctx, wo_w, wo_b, x, x1, ROWS, D_MODEL, D_MODEL);
    // 5) ln2
    ln_kernel<<<ROWS, 256>>>(x1, ln2_g, ln2_b, h2);
    // 6) fc1 + exact GELU
    gemm_kernel<1><<<dim3(D_FF / 128, ROWS / 128), 256>>>(h2, fc1_w, fc1_b, nullptr, ff, ROWS, D_FF, D_MODEL);
    // 7) fc2 + residual -> out
    gemm_kernel<2><<<gD, 256>>>(ff, fc2_w, fc2_b, x1, out, ROWS, D_MODEL, D_FF);
}

// round 5
// speedup vs baseline: 2.6678x; 2.6678x over previous
#include <cuda_runtime.h>
#include <cuda_fp16.h>
#include <math.h>
#include <stdint.h>

#define D_MODEL 1024
#define N_HEADS 16
#define HEAD_DIM 64
#define D_FF 4096
#define BB 2
#define TT 2048
#define ROWS (BB * TT)
#define LN_EPS 1e-5f

// ---------------- scratch (static device globals; no allocation) ----------------
__device__ float  g_q  [ROWS * D_MODEL];
__device__ float  g_k  [ROWS * D_MODEL];
__device__ float  g_v  [ROWS * D_MODEL];
__device__ float  g_x1 [ROWS * D_MODEL];
__device__ __half g_hh  [ROWS * D_MODEL];
__device__ __half g_h2h [ROWS * D_MODEL];
__device__ __half g_ctxh[ROWS * D_MODEL];
__device__ __half g_ffh [ROWS * D_FF];
__device__ __half g_wqh [D_MODEL * D_MODEL];
__device__ __half g_wkh [D_MODEL * D_MODEL];
__device__ __half g_wvh [D_MODEL * D_MODEL];
__device__ __half g_woh [D_MODEL * D_MODEL];
__device__ __half g_fc1h[D_FF * D_MODEL];
__device__ __half g_fc2h[D_MODEL * D_FF];

// ---------------- small asm wrappers ----------------
__device__ __forceinline__ void cp_async16(uint32_t dst, const void* src)
{
    asm volatile("cp.async.cg.shared.global [%0], [%1], 16;" :: "r"(dst), "l"(src));
}
__device__ __forceinline__ void cp_commit()
{
    asm volatile("cp.async.commit_group;");
}
__device__ __forceinline__ void cp_wait1()
{
    asm volatile("cp.async.wait_group 1;");
}
__device__ __forceinline__ void cp_wait0()
{
    asm volatile("cp.async.wait_group 0;");
}
__device__ __forceinline__ void ldsm4(uint32_t* r, uint32_t addr)
{
    asm volatile("ldmatrix.sync.aligned.m8n8.x4.shared.b16 {%0,%1,%2,%3}, [%4];"
                 : "=r"(r[0]), "=r"(r[1]), "=r"(r[2]), "=r"(r[3]) : "r"(addr));
}
__device__ __forceinline__ void mma16816(float* d, const uint32_t* a, const uint32_t* b)
{
    asm volatile("mma.sync.aligned.m16n8k16.row.col.f32.f16.f16.f32 "
                 "{%0,%1,%2,%3}, {%4,%5,%6,%7}, {%8,%9}, {%0,%1,%2,%3};"
                 : "+f"(d[0]), "+f"(d[1]), "+f"(d[2]), "+f"(d[3])
                 : "r"(a[0]), "r"(a[1]), "r"(a[2]), "r"(a[3]), "r"(b[0]), "r"(b[1]));
}

// ---------------- fp32 -> fp16 ----------------
__global__ __launch_bounds__(256) void f2h_kernel(const float* __restrict__ s,
                                                  __half* __restrict__ d, int n)
{
    int i = (blockIdx.x * 256 + threadIdx.x) * 4;
    if (i < n) {
        float4 v = *(const float4*)(s + i);
        __half2 p0 = __floats2half2_rn(v.x, v.y);
        __half2 p1 = __floats2half2_rn(v.z, v.w);
        *(__half2*)(d + i) = p0;
        *(__half2*)(d + i + 2) = p1;
    }
}

// ---------------- LayerNorm -> half ----------------
__global__ __launch_bounds__(256) void ln_kernel(const float* __restrict__ x,
                                                 const float* __restrict__ gam,
                                                 const float* __restrict__ bet,
                                                 __half* __restrict__ y)
{
    const int row = blockIdx.x;
    const int tid = threadIdx.x;
    float4 v = ((const float4*)(x + (size_t)row * D_MODEL))[tid];
    float s  = v.x + v.y + v.z + v.w;
    float ss = v.x * v.x + v.y * v.y + v.z * v.z + v.w * v.w;
    #pragma unroll
    for (int o = 16; o > 0; o >>= 1) {
        s  += __shfl_xor_sync(0xffffffffu, s, o);
        ss += __shfl_xor_sync(0xffffffffu, ss, o);
    }
    __shared__ float wsum[8];
    __shared__ float wsq[8];
    const int wi = tid >> 5;
    const int la = tid & 31;
    if (la == 0) { wsum[wi] = s; wsq[wi] = ss; }
    __syncthreads();
    s = 0.f; ss = 0.f;
    #pragma unroll
    for (int i = 0; i < 8; i++) { s += wsum[i]; ss += wsq[i]; }
    const float mean = s * (1.f / D_MODEL);
    const float var  = ss * (1.f / D_MODEL) - mean * mean;
    const float rstd = rsqrtf(var + LN_EPS);
    float4 g4 = ((const float4*)gam)[tid];
    float4 b4 = ((const float4*)bet)[tid];
    float o0 = (v.x - mean) * rstd * g4.x + b4.x;
    float o1 = (v.y - mean) * rstd * g4.y + b4.y;
    float o2 = (v.z - mean) * rstd * g4.z + b4.z;
    float o3 = (v.w - mean) * rstd * g4.w + b4.w;
    __half* yp = y + (size_t)row * D_MODEL + tid * 4;
    __half2 q0 = __floats2half2_rn(o0, o1);
    __half2 q1 = __floats2half2_rn(o2, o3);
    *(__half2*)(yp) = q0;
    *(__half2*)(yp + 2) = q1;
}

// ---------------- HGEMM: C[M,N] = A[M,K] @ W[N,K]^T + bias (+epilogue) ----------------
// EPI: 0 none, 1 exact GELU, 2 +residual.  OUTH: 0 -> float out, 1 -> half out.
#define SROW 40   // smem row pitch in halves (80B) -> conflict-free LDSM

template<int EPI, int OUTH>
__global__ __launch_bounds__(256, 2) void hgemm_kernel(
    const __half* __restrict__ A, const __half* __restrict__ W,
    const float* __restrict__ bias, const float* __restrict__ res,
    void* __restrict__ Cv, int M, int N, int K)
{
    __shared__ __half As[2][128 * SROW];
    __shared__ __half Ws[2][128 * SROW];

    const int tid = threadIdx.x;
    const int bm = blockIdx.y * 128;
    const int bn = blockIdx.x * 128;
    const int lrow = tid >> 1;
    const int lcol = (tid & 1) * 16;
    const __half* Ag = A + (size_t)(bm + lrow) * K + lcol;
    const __half* Wg = W + (size_t)(bn + lrow) * K + lcol;

    uint32_t aS0 = (uint32_t)__cvta_generic_to_shared(&As[0][0]);
    uint32_t aS1 = (uint32_t)__cvta_generic_to_shared(&As[1][0]);
    uint32_t wS0 = (uint32_t)__cvta_generic_to_shared(&Ws[0][0]);
    uint32_t wS1 = (uint32_t)__cvta_generic_to_shared(&Ws[1][0]);
    const uint32_t stOff = (uint32_t)(lrow * SROW + lcol) * 2u;

    const int lane = tid & 31;
    const int wid = tid >> 5;
    const int wm = (wid >> 1) * 32;
    const int wn = (wid & 1) * 64;

    // A frags: lanes 0-7 rows 0-7 k0 | 8-15 rows 8-15 k0 | 16-23 rows 0-7 k8 | 24-31 rows 8-15 k8
    const uint32_t aFragOff = (uint32_t)((wm + (lane & 15)) * SROW + (lane >> 4) * 8) * 2u;
    // B frags: lanes 0-7 n0-7 k0 | 8-15 n0-7 k8 | 16-23 n8-15 k0 | 24-31 n8-15 k8
    const uint32_t bFragOff = (uint32_t)((wn + (lane & 7) + ((lane >> 4) << 3)) * SROW
                                         + ((lane >> 3) & 1) * 8) * 2u;

    float acc[2][8][4];
    #pragma unroll
    for (int i = 0; i < 2; i++)
        #pragma unroll
        for (int j = 0; j < 8; j++)
            #pragma unroll
            for (int t = 0; t < 4; t++)
                acc[i][j][t] = 0.f;

    const int NK = K / 32;

    // prologue: tile 0 -> buf 0
    cp_async16(aS0 + stOff, Ag);
    cp_async16(aS0 + stOff + 16, Ag + 8);
    cp_async16(wS0 + stOff, Wg);
    cp_async16(wS0 + stOff + 16, Wg + 8);
    cp_commit();

    for (int it = 0; it < NK; it++) {
        const uint32_t aB = (it & 1) ? aS1 : aS0;
        const uint32_t wB = (it & 1) ? wS1 : wS0;
        if (it + 1 < NK) {
            const uint32_t aN = (it & 1) ? aS0 : aS1;
            const uint32_t wN = (it & 1) ? wS0 : wS1;
            const __half* an = Ag + (it + 1) * 32;
            const __half* wn2 = Wg + (it + 1) * 32;
            cp_async16(aN + stOff, an);
            cp_async16(aN + stOff + 16, an + 8);
            cp_async16(wN + stOff, wn2);
            cp_async16(wN + stOff + 16, wn2 + 8);
            cp_commit();
            cp_wait1();
        } else {
            cp_wait0();
        }
        __syncthreads();

        #pragma unroll
        for (int ks = 0; ks < 2; ks++) {
            uint32_t a0[4];
            uint32_t a1[4];
            ldsm4(a0, aB + aFragOff + ks * 32);
            ldsm4(a1, aB + aFragOff + 16 * SROW * 2 + ks * 32);
            uint32_t bfr[4][4];
            #pragma unroll
            for (int p = 0; p < 4; p++) {
                ldsm4(bfr[p], wB + bFragOff + p * 16 * SROW * 2 + ks * 32);
            }
            #pragma unroll
            for (int p = 0; p < 4; p++) {
                mma16816(acc[0][p * 2 + 0], a0, &bfr[p][0]);
                mma16816(acc[0][p * 2 + 1], a0, &bfr[p][2]);
                mma16816(acc[1][p * 2 + 0], a1, &bfr[p][0]);
                mma16816(acc[1][p * 2 + 1], a1, &bfr[p][2]);
            }
        }
        __syncthreads();
    }

    // epilogue
    const int gq = lane >> 2;
    const int t2 = (lane & 3) * 2;
    #pragma unroll
    for (int mi = 0; mi < 2; mi++) {
        #pragma unroll
        for (int nj = 0; nj < 8; nj++) {
            const int c = bn + wn + nj * 8 + t2;
            const float b0 = bias[c];
            const float b1 = bias[c + 1];
            #pragma unroll
            for (int hm = 0; hm < 2; hm++) {
                const int r = bm + wm + mi * 16 + gq + hm * 8;
                float v0 = acc[mi][nj][hm * 2 + 0] + b0;
                float v1 = acc[mi][nj][hm * 2 + 1] + b1;
                if (EPI == 1) {
                    v0 = 0.5f * v0 * (1.f + erff(v0 * 0.70710678f));
                    v1 = 0.5f * v1 * (1.f + erff(v1 * 0.70710678f));
                }
                if (EPI == 2) {
                    float2 rv = *(const float2*)(res + (size_t)r * N + c);
                    v0 += rv.x;
                    v1 += rv.y;
                }
                if (OUTH == 1) {
                    __half2 hv = __floats2half2_rn(v0, v1);
                    *(__half2*)((__half*)Cv + (size_t)r * N + c) = hv;
                } else {
                    *(float2*)((float*)Cv + (size_t)r * N + c) = make_float2(v0, v1);
                }
            }
        }
    }
}

// ---------------- Flash attention (causal), fp32 math, half out ----------------
#define APAD 65
#define ATTN_SMEM (4 * 64 * APAD * (int)sizeof(float))

__global__ __launch_bounds__(256) void attn_kernel(
    const float* __restrict__ Q, const float* __restrict__ K,
    const float* __restrict__ V, __half* __restrict__ O)
{
    extern __shared__ float sm[];
    float* Qs = sm;
    float* Ks = sm + 64 * APAD;
    float* Vs = sm + 2 * 64 * APAD;
    float* Ps = sm + 3 * 64 * APAD;

    const int qt = blockIdx.x;
    const int hd = blockIdx.y;
    const int bz = blockIdx.z;
    const int tid = threadIdx.x;
    const int tx = tid & 15;
    const int ty = tid >> 4;
    const int q0 = qt * 64;
    const size_t base = (size_t)bz * TT * D_MODEL + (size_t)hd * HEAD_DIM;

    #pragma unroll
    for (int i = 0; i < 4; i++) {
        int lin = tid + i * 256;
        int row = lin >> 4;
        int c4 = lin & 15;
        float4 qv = *(const float4*)(Q + base + (size_t)(q0 + row) * D_MODEL + c4 * 4);
        float* d = Qs + row * APAD + c4 * 4;
        d[0] = qv.x; d[1] = qv.y; d[2] = qv.z; d[3] = qv.w;
    }

    float m_run[4] = {-1e30f, -1e30f, -1e30f, -1e30f};
    float l_run[4] = {0.f, 0.f, 0.f, 0.f};
    float oacc[4][4];
    #pragma unroll
    for (int i = 0; i < 4; i++)
        #pragma unroll
        for (int j = 0; j < 4; j++)
            oacc[i][j] = 0.f;

    for (int kt = 0; kt <= qt; kt++) {
        const int k0 = kt * 64;
        __syncthreads();
        #pragma unroll
        for (int i = 0; i < 4; i++) {
            int lin = tid + i * 256;
            int row = lin >> 4;
            int c4 = lin & 15;
            const size_t goff = base + (size_t)(k0 + row) * D_MODEL + c4 * 4;
            float4 kv = *(const float4*)(K + goff);
            float4 vv = *(const float4*)(V + goff);
            float* dk = Ks + row * APAD + c4 * 4;
            float* dv = Vs + row * APAD + c4 * 4;
            dk[0] = kv.x; dk[1] = kv.y; dk[2] = kv.z; dk[3] = kv.w;
            dv[0] = vv.x; dv[1] = vv.y; dv[2] = vv.z; dv[3] = vv.w;
        }
        __syncthreads();

        float s[4][4];
        #pragma unroll
        for (int i = 0; i < 4; i++)
            #pragma unroll
            for (int j = 0; j < 4; j++)
                s[i][j] = 0.f;

        #pragma unroll 4
        for (int d = 0; d < 64; d++) {
            float a[4];
            float kb[4];
            #pragma unroll
            for (int i = 0; i < 4; i++) a[i] = Qs[(ty * 4 + i) * APAD + d];
            #pragma unroll
            for (int j = 0; j < 4; j++) kb[j] = Ks[(tx * 4 + j) * APAD + d];
            #pragma unroll
            for (int i = 0; i < 4; i++)
                #pragma unroll
                for (int j = 0; j < 4; j++)
                    s[i][j] += a[i] * kb[j];
        }

        if (kt == qt) {
            #pragma unroll
            for (int i = 0; i < 4; i++)
                #pragma unroll
                for (int j = 0; j < 4; j++) {
                    int qr = ty * 4 + i;
                    int kc = tx * 4 + j;
                    s[i][j] = (kc > qr) ? -1e9f : s[i][j] * 0.125f;
                }
        } else {
            #pragma unroll
            for (int i = 0; i < 4; i++)
                #pragma unroll
                for (int j = 0; j < 4; j++)
                    s[i][j] *= 0.125f;
        }

        float osc[4];
        #pragma unroll
        for (int i = 0; i < 4; i++) {
            float mt = fmaxf(fmaxf(s[i][0], s[i][1]), fmaxf(s[i][2], s[i][3]));
            mt = fmaxf(mt, __shfl_xor_sync(0xffffffffu, mt, 1));
            mt = fmaxf(mt, __shfl_xor_sync(0xffffffffu, mt, 2));
            mt = fmaxf(mt, __shfl_xor_sync(0xffffffffu, mt, 4));
            mt = fmaxf(mt, __shfl_xor_sync(0xffffffffu, mt, 8));
            float mn = fmaxf(m_run[i], mt);
            float esc = expf(m_run[i] - mn);
            float ps = 0.f;
            #pragma unroll
            for (int j = 0; j < 4; j++) {
                float p = expf(s[i][j] - mn);
                Ps[(ty * 4 + i) * APAD + tx * 4 + j] = p;
                ps += p;
            }
            ps += __shfl_xor_sync(0xffffffffu, ps, 1);
            ps += __shfl_xor_sync(0xffffffffu, ps, 2);
            ps += __shfl_xor_sync(0xffffffffu, ps, 4);
            ps += __shfl_xor_sync(0xffffffffu, ps, 8);
            l_run[i] = l_run[i] * esc + ps;
            m_run[i] = mn;
            osc[i] = esc;
        }
        #pragma unroll
        for (int i = 0; i < 4; i++)
            #pragma unroll
            for (int dd = 0; dd < 4; dd++)
                oacc[i][dd] *= osc[i];

        __syncwarp();

        #pragma unroll 4
        for (int j = 0; j < 64; j++) {
            float pv[4];
            float vv[4];
            #pragma unroll
            for (int i = 0; i < 4; i++) pv[i] = Ps[(ty * 4 + i) * APAD + j];
            #pragma unroll
            for (int dd = 0; dd < 4; dd++) vv[dd] = Vs[j * APAD + tx * 4 + dd];
            #pragma unroll
            for (int i = 0; i < 4; i++)
                #pragma unroll
                for (int dd = 0; dd < 4; dd++)
                    oacc[i][dd] += pv[i] * vv[dd];
        }
    }

    #pragma unroll
    for (int i = 0; i < 4; i++) {
        float inv = 1.f / l_run[i];
        __half* op = O + base + (size_t)(q0 + ty * 4 + i) * D_MODEL + tx * 4;
        __half2 p0 = __floats2half2_rn(oacc[i][0] * inv, oacc[i][1] * inv);
        __half2 p1 = __floats2half2_rn(oacc[i][2] * inv, oacc[i][3] * inv);
        *(__half2*)(op) = p0;
        *(__half2*)(op + 2) = p1;
    }
}

// ---------------- launch ----------------
extern "C" void kernel_launch(void* const* d_in, const int* in_sizes, int n_in,
                              void* d_out, int out_size)
{
    const float* x     = (const float*)d_in[0];
    const float* wq_w  = (const float*)d_in[2];
    const float* wq_b  = (const float*)d_in[3];
    const float* wk_w  = (const float*)d_in[4];
    const float* wk_b  = (const float*)d_in[5];
    const float* wv_w  = (const float*)d_in[6];
    const float* wv_b  = (const float*)d_in[7];
    const float* wo_w  = (const float*)d_in[8];
    const float* wo_b  = (const float*)d_in[9];
    const float* fc1_w = (const float*)d_in[10];
    const float* fc1_b = (const float*)d_in[11];
    const float* fc2_w = (const float*)d_in[12];
    const float* fc2_b = (const float*)d_in[13];
    const float* ln1_g = (const float*)d_in[14];
    const float* ln1_b = (const float*)d_in[15];
    const float* ln2_g = (const float*)d_in[16];
    const float* ln2_b = (const float*)d_in[17];
    float* out = (float*)d_out;

    void* p = 0;
    cudaGetSymbolAddress(&p, g_q);    float* q = (float*)p;
    cudaGetSymbolAddress(&p, g_k);    float* k = (float*)p;
    cudaGetSymbolAddress(&p, g_v);    float* v = (float*)p;
    cudaGetSymbolAddress(&p, g_x1);   float* x1 = (float*)p;
    cudaGetSymbolAddress(&p, g_hh);   __half* hh = (__half*)p;
    cudaGetSymbolAddress(&p, g_h2h);  __half* h2h = (__half*)p;
    cudaGetSymbolAddress(&p, g_ctxh); __half* ctxh = (__half*)p;
    cudaGetSymbolAddress(&p, g_ffh);  __half* ffh = (__half*)p;
    cudaGetSymbolAddress(&p, g_wqh);  __half* wqh = (__half*)p;
    cudaGetSymbolAddress(&p, g_wkh);  __half* wkh = (__half*)p;
    cudaGetSymbolAddress(&p, g_wvh);  __half* wvh = (__half*)p;
    cudaGetSymbolAddress(&p, g_woh);  __half* woh = (__half*)p;
    cudaGetSymbolAddress(&p, g_fc1h); __half* fc1h = (__half*)p;
    cudaGetSymbolAddress(&p, g_fc2h); __half* fc2h = (__half*)p;

    cudaFuncSetAttribute(attn_kernel, cudaFuncAttributeMaxDynamicSharedMemorySize, ATTN_SMEM);

    const int nW = D_MODEL * D_MODEL;
    const int nF = D_FF * D_MODEL;
    f2h_kernel<<<nW / 1024, 256>>>(wq_w, wqh, nW);
    f2h_kernel<<<nW / 1024, 256>>>(wk_w, wkh, nW);
    f2h_kernel<<<nW / 1024, 256>>>(wv_w, wvh, nW);
    f2h_kernel<<<nW / 1024, 256>>>(wo_w, woh, nW);
    f2h_kernel<<<nF / 1024, 256>>>(fc1_w, fc1h, nF);
    f2h_kernel<<<nF / 1024, 256>>>(fc2_w, fc2h, nF);

    dim3 gD(D_MODEL / 128, ROWS / 128);
    dim3 gF(D_FF / 128, ROWS / 128);

    ln_kernel<<<ROWS, 256>>>(x, ln1_g, ln1_b, hh);
    hgemm_kernel<0, 0><<<gD, 256>>>(hh, wqh, wq_b, 0, q, ROWS, D_MODEL, D_MODEL);
    hgemm_kernel<0, 0><<<gD, 256>>>(hh, wkh, wk_b, 0, k, ROWS, D_MODEL, D_MODEL);
    hgemm_kernel<0, 0><<<gD, 256>>>(hh, wvh, wv_b, 0, v, ROWS, D_MODEL, D_MODEL);
    attn_kernel<<<dim3(TT / 64, N_HEADS, BB), 256, ATTN_SMEM>>>(q, k, v, ctxh);
    hgemm_kernel<2, 0><<<gD, 256>>>(ctxh, woh, wo_b, x, x1, ROWS, D_MODEL, D_MODEL);
    ln_kernel<<<ROWS, 256>>>(x1, ln2_g, ln2_b, h2h);
    hgemm_kernel<1, 1><<<gF, 256>>>(h2h, fc1h, fc1_b, 0, ffh, ROWS, D_FF, D_MODEL);
    hgemm_kernel<2, 0><<<gD, 256>>>(ffh, fc2h, fc2_b, x1, out, ROWS, D_MODEL, D_FF);
}